// round 16
// baseline (speedup 1.0000x reference)
#include <cuda_runtime.h>
#include <math.h>
#include <stdint.h>

#define N_PTS 32768
#define DIM   512
#define NC    64
#define KM_ITERS 10

#define ACC_BLOCKS 128
#define CHUNK (N_PTS / ACC_BLOCKS)   // 256

#define KC 64
#define XS_STRIDE 132   // 128 + 4 pad
#define WS_STRIDE 72    // 64 + 8 pad
#define SMEM_GEMM ((KC * XS_STRIDE + KC * WS_STRIDE) * 4)   // 52224 B

// ---- scratch (no allocations allowed) ----
__device__ float g_centers[NC * DIM];
__device__ float g_b2p[NC * 16];     // per-cluster ||c||^2 in 16 partials
__device__ int   g_assign[N_PTS];
__device__ float g_psum[(size_t)ACC_BLOCKS * NC * DIM];   // 16 MB partials
__device__ float g_pcnt[ACC_BLOCKS * NC];

// ============================================================================
// init: centers = data[:64], b2 partials.   grid 64, block 128
// ============================================================================
__global__ void init_kernel(const float* __restrict__ X) {
    int c = blockIdx.x;
    int t = threadIdx.x;           // 0..127, handles 4 dims via float4
    const float4* xr = (const float4*)(X + (size_t)c * DIM);
    float4 v = xr[t];
    ((float4*)(g_centers + (size_t)c * DIM))[t] = v;
    float s = v.x * v.x + v.y * v.y + v.z * v.z + v.w * v.w;
    __shared__ float red[128];
    red[t] = s;
    __syncthreads();
    for (int o = 64; o > 0; o >>= 1) {
        if (t < o) red[t] += red[t + o];
        __syncthreads();
    }
    if (t < 16) g_b2p[c * 16 + t] = (t == 0) ? red[0] : 0.0f;
}

// ============================================================================
// assign: argmin_c ( b2[c] - 2 * x . c )   (dropping constant ||x||^2)
// block tile: 128 points x 64 clusters, 256 threads, thread tile 4x8, KC=64
// grid = N_PTS/128 = 256.  (scalar FFMA mainloop)
// ============================================================================
__global__ __launch_bounds__(256) void assign_kernel(const float* __restrict__ X) {
    extern __shared__ __align__(16) float dynsm[];
    float* Xs = dynsm;                        // KC * XS_STRIDE
    float* Ws = dynsm + KC * XS_STRIDE;       // KC * WS_STRIDE
    __shared__ float sb2[NC];
    __shared__ float sval[128 * 8];
    __shared__ int   sidx[128 * 8];

    int tid = threadIdx.x;
    int tx = tid & 31;        // point group: points 4*tx .. 4*tx+3
    int ty = tid >> 5;        // cluster group: clusters 8*ty .. 8*ty+7
    int P0 = blockIdx.x * 128;

    if (tid < NC) {
        const float* bp = g_b2p + tid * 16;
        float s = 0.0f;
#pragma unroll
        for (int g = 0; g < 16; g++) s += bp[g];
        sb2[tid] = s;
    }

    float acc[4][8];
#pragma unroll
    for (int i = 0; i < 4; i++)
#pragma unroll
        for (int j = 0; j < 8; j++) acc[i][j] = 0.0f;

    const float4* X4 = (const float4*)X;
    const float4* W4 = (const float4*)g_centers;

    for (int kc4 = 0; kc4 < DIM / 4; kc4 += KC / 4) {
        // load 128x64 X tile, transposed into Xs[k][p]
#pragma unroll
        for (int r = 0; r < 8; r++) {
            int q = tid + r * 256;           // 0..2047
            int p = q >> 4;                  // 0..127
            int j = q & 15;                  // float4 within the 64-k chunk
            float4 v = X4[(size_t)(P0 + p) * (DIM / 4) + kc4 + j];
            int kk = j * 4;
            Xs[(kk + 0) * XS_STRIDE + p] = v.x;
            Xs[(kk + 1) * XS_STRIDE + p] = v.y;
            Xs[(kk + 2) * XS_STRIDE + p] = v.z;
            Xs[(kk + 3) * XS_STRIDE + p] = v.w;
        }
        // load 64x64 W tile, transposed into Ws[k][c]
#pragma unroll
        for (int r = 0; r < 4; r++) {
            int q = tid + r * 256;           // 0..1023
            int c = q >> 4;                  // 0..63
            int j = q & 15;
            float4 v = W4[(size_t)c * (DIM / 4) + kc4 + j];
            int kk = j * 4;
            Ws[(kk + 0) * WS_STRIDE + c] = v.x;
            Ws[(kk + 1) * WS_STRIDE + c] = v.y;
            Ws[(kk + 2) * WS_STRIDE + c] = v.z;
            Ws[(kk + 3) * WS_STRIDE + c] = v.w;
        }
        __syncthreads();
#pragma unroll 8
        for (int k = 0; k < KC; k++) {
            float xr[4], wr[8];
            *(float4*)&xr[0] = *(const float4*)&Xs[k * XS_STRIDE + tx * 4];
            *(float4*)&wr[0] = *(const float4*)&Ws[k * WS_STRIDE + ty * 8];
            *(float4*)&wr[4] = *(const float4*)&Ws[k * WS_STRIDE + ty * 8 + 4];
#pragma unroll
            for (int i = 0; i < 4; i++)
#pragma unroll
                for (int j = 0; j < 8; j++)
                    acc[i][j] += xr[i] * wr[j];
        }
        __syncthreads();
    }

    // per-thread argmin over its 8 clusters (ascending index, strict <)
#pragma unroll
    for (int i = 0; i < 4; i++) {
        float mv = 3.4e38f;
        int mi = 0;
#pragma unroll
        for (int j = 0; j < 8; j++) {
            float s = sb2[ty * 8 + j] - 2.0f * acc[i][j];
            if (s < mv) { mv = s; mi = ty * 8 + j; }
        }
        int p = tx * 4 + i;
        sval[p * 8 + ty] = mv;
        sidx[p * 8 + ty] = mi;
    }
    __syncthreads();
    // reduce 8 candidates per point (ascending ty == ascending cluster ranges)
    if (tid < 128) {
        float mv = sval[tid * 8];
        int mi = sidx[tid * 8];
#pragma unroll
        for (int t = 1; t < 8; t++) {
            float v = sval[tid * 8 + t];
            if (v < mv) { mv = v; mi = sidx[tid * 8 + t]; }
        }
        g_assign[P0 + tid] = mi;
    }
}

// ============================================================================
// accumulate: per-block shared accumulator (64x512 fp32 = 128 KB), warp-private
// dim slices, 8-point batching. grid ACC_BLOCKS, block 256.
// ============================================================================
__global__ __launch_bounds__(256) void accum_kernel(const float* __restrict__ X) {
    extern __shared__ float sm[];
    float* sacc = sm;                       // NC*DIM
    float* scnt = sm + NC * DIM;            // NC
    int*   sassign = (int*)(scnt + NC);     // CHUNK

    int tid = threadIdx.x;
    int base = blockIdx.x * CHUNK;
    for (int i = tid; i < CHUNK; i += 256) sassign[i] = g_assign[base + i];
    float4* sacc4 = (float4*)sacc;
    for (int i = tid; i < NC * DIM / 4; i += 256)
        sacc4[i] = make_float4(0.f, 0.f, 0.f, 0.f);
    for (int i = tid; i < NC; i += 256) scnt[i] = 0.0f;
    __syncthreads();

    int w = tid >> 5, lane = tid & 31;
    int doff = w * 32 + lane;               // float2 offset: warp w owns dims [64w,64w+64)
    const float2* X2 = (const float2*)X;
    float2* sacc2 = (float2*)sacc;

    for (int p = 0; p < CHUNK; p += 8) {
        float2 v[8];
        int a[8];
#pragma unroll
        for (int q = 0; q < 8; q++) {
            a[q] = sassign[p + q];
            v[q] = X2[(size_t)(base + p + q) * (DIM / 2) + doff];
        }
#pragma unroll
        for (int q = 0; q < 8; q++) {
            float2* ap = &sacc2[a[q] * (DIM / 2) + doff];
            float2 cur = *ap;
            cur.x += v[q].x; cur.y += v[q].y;
            *ap = cur;
        }
    }
    __syncthreads();
    for (int i = tid; i < CHUNK; i += 256) atomicAdd(&scnt[sassign[i]], 1.0f);
    __syncthreads();

    float4* ps4 = (float4*)(g_psum + (size_t)blockIdx.x * NC * DIM);
    for (int i = tid; i < NC * DIM / 4; i += 256) ps4[i] = sacc4[i];
    if (tid < NC) g_pcnt[blockIdx.x * NC + tid] = scnt[tid];
}

// ============================================================================
// update1: reduce partials -> new centers (keep old if empty) + b2 partials.
// grid NC*16 (cluster c = bid>>4, 32-dim group = bid&15),
// block 128 = 32 dims x 4 b-slices (32 partials each, MLP 8).
// ============================================================================
__global__ __launch_bounds__(128) void update1_kernel() {
    int c = blockIdx.x >> 4;
    int dg = blockIdx.x & 15;
    int t = threadIdx.x;
    int dl = t & 31;             // dim within the 32-dim group
    int slice = t >> 5;          // b-slice 0..3
    int d = dg * 32 + dl;
    __shared__ float part[4][32];
    __shared__ float s_cnt;

    // count for this cluster: one warp, 4 loads + shfl reduce (exact: integers)
    if (t < 32) {
        float cs = 0.0f;
#pragma unroll
        for (int s = 0; s < 4; s++) cs += g_pcnt[(t + s * 32) * NC + c];
#pragma unroll
        for (int o = 16; o > 0; o >>= 1) cs += __shfl_down_sync(0xffffffffu, cs, o);
        if (t == 0) s_cnt = cs;
    }

    // partial-sum 32 of the 128 psum slices, MLP 8
    const float* ps = g_psum + (size_t)c * DIM + d + (size_t)(slice * 32) * (NC * DIM);
    float a[8];
#pragma unroll
    for (int r = 0; r < 8; r++) a[r] = 0.0f;
#pragma unroll
    for (int b = 0; b < 32; b += 8) {
#pragma unroll
        for (int r = 0; r < 8; r++) a[r] += ps[(size_t)(b + r) * (NC * DIM)];
    }
    part[slice][dl] = ((a[0] + a[1]) + (a[2] + a[3])) + ((a[4] + a[5]) + (a[6] + a[7]));
    __syncthreads();

    if (t < 32) {
        float s = (part[0][dl] + part[1][dl]) + (part[2][dl] + part[3][dl]);
        float cnt = s_cnt;
        float oldc = g_centers[c * DIM + d];
        float nc = (cnt > 0.0f) ? s / cnt : oldc;
        g_centers[c * DIM + d] = nc;
        // b2 partial for this 32-dim group
        float q = nc * nc;
#pragma unroll
        for (int o = 16; o > 0; o >>= 1) q += __shfl_down_sync(0xffffffffu, q, o);
        if (t == 0) g_b2p[c * 16 + dg] = q;
    }
}

// ============================================================================
// final: out[p][c] = 1 / (sqrt(max(||x||^2 + ||c||^2 - 2 x.c, 0)) + 1e-8)
// same GEMM structure; ||x||^2 fused into warp ty==0 of the mainloop
// ============================================================================
__global__ __launch_bounds__(256) void final_kernel(const float* __restrict__ X,
                                                    float* __restrict__ out) {
    extern __shared__ __align__(16) float dynsm[];
    float* Xs = dynsm;
    float* Ws = dynsm + KC * XS_STRIDE;
    __shared__ float sb2[NC];
    __shared__ float sa2[128];

    int tid = threadIdx.x;
    int tx = tid & 31, ty = tid >> 5;
    int P0 = blockIdx.x * 128;

    if (tid < NC) {
        const float* bp = g_b2p + tid * 16;
        float s = 0.0f;
#pragma unroll
        for (int g = 0; g < 16; g++) s += bp[g];
        sb2[tid] = s;
    }

    float acc[4][8];
#pragma unroll
    for (int i = 0; i < 4; i++)
#pragma unroll
        for (int j = 0; j < 8; j++) acc[i][j] = 0.0f;
    float a2acc[4] = {0.f, 0.f, 0.f, 0.f};

    const float4* X4 = (const float4*)X;
    const float4* W4 = (const float4*)g_centers;

    for (int kc4 = 0; kc4 < DIM / 4; kc4 += KC / 4) {
#pragma unroll
        for (int r = 0; r < 8; r++) {
            int q = tid + r * 256;
            int p = q >> 4;
            int j = q & 15;
            float4 v = X4[(size_t)(P0 + p) * (DIM / 4) + kc4 + j];
            int kk = j * 4;
            Xs[(kk + 0) * XS_STRIDE + p] = v.x;
            Xs[(kk + 1) * XS_STRIDE + p] = v.y;
            Xs[(kk + 2) * XS_STRIDE + p] = v.z;
            Xs[(kk + 3) * XS_STRIDE + p] = v.w;
        }
#pragma unroll
        for (int r = 0; r < 4; r++) {
            int q = tid + r * 256;
            int c = q >> 4;
            int j = q & 15;
            float4 v = W4[(size_t)c * (DIM / 4) + kc4 + j];
            int kk = j * 4;
            Ws[(kk + 0) * WS_STRIDE + c] = v.x;
            Ws[(kk + 1) * WS_STRIDE + c] = v.y;
            Ws[(kk + 2) * WS_STRIDE + c] = v.z;
            Ws[(kk + 3) * WS_STRIDE + c] = v.w;
        }
        __syncthreads();
#pragma unroll 8
        for (int k = 0; k < KC; k++) {
            float xr[4], wr[8];
            *(float4*)&xr[0] = *(const float4*)&Xs[k * XS_STRIDE + tx * 4];
            *(float4*)&wr[0] = *(const float4*)&Ws[k * WS_STRIDE + ty * 8];
            *(float4*)&wr[4] = *(const float4*)&Ws[k * WS_STRIDE + ty * 8 + 4];
            if (ty == 0) {
#pragma unroll
                for (int i = 0; i < 4; i++) a2acc[i] += xr[i] * xr[i];
            }
#pragma unroll
            for (int i = 0; i < 4; i++)
#pragma unroll
                for (int j = 0; j < 8; j++)
                    acc[i][j] += xr[i] * wr[j];
        }
        __syncthreads();
    }

    if (ty == 0) {
#pragma unroll
        for (int i = 0; i < 4; i++) sa2[tx * 4 + i] = a2acc[i];
    }
    __syncthreads();

#pragma unroll
    for (int i = 0; i < 4; i++) {
        float a2 = sa2[tx * 4 + i];
        float res[8];
#pragma unroll
        for (int j = 0; j < 8; j++) {
            float d2 = a2 + sb2[ty * 8 + j] - 2.0f * acc[i][j];
            d2 = fmaxf(d2, 0.0f);
            res[j] = 1.0f / (sqrtf(d2) + 1e-8f);
        }
        float* op = out + (size_t)(P0 + tx * 4 + i) * NC + ty * 8;
        *(float4*)&op[0] = *(float4*)&res[0];
        *(float4*)&op[4] = *(float4*)&res[4];
    }
}

// ============================================================================
extern "C" void kernel_launch(void* const* d_in, const int* in_sizes, int n_in,
                              void* d_out, int out_size) {
    const float* X = (const float*)d_in[0];
    float* out = (float*)d_out;

    const int smem_acc = (NC * DIM + NC + CHUNK) * 4;   // ~132.3 KB
    cudaFuncSetAttribute(accum_kernel,
                         cudaFuncAttributeMaxDynamicSharedMemorySize, smem_acc);
    cudaFuncSetAttribute(assign_kernel,
                         cudaFuncAttributeMaxDynamicSharedMemorySize, SMEM_GEMM);
    cudaFuncSetAttribute(final_kernel,
                         cudaFuncAttributeMaxDynamicSharedMemorySize, SMEM_GEMM);

    init_kernel<<<NC, 128>>>(X);
    for (int it = 0; it < KM_ITERS; it++) {
        assign_kernel<<<N_PTS / 128, 256, SMEM_GEMM>>>(X);
        accum_kernel<<<ACC_BLOCKS, 256, smem_acc>>>(X);
        update1_kernel<<<NC * 16, 128>>>();
    }
    final_kernel<<<N_PTS / 128, 256, SMEM_GEMM>>>(X, out);
}

// round 17
// speedup vs baseline: 1.1611x; 1.1611x over previous
#include <cuda_runtime.h>
#include <math.h>
#include <stdint.h>

#define N_PTS 32768
#define DIM   512
#define NC    64
#define KM_ITERS 10

#define ACC_BLOCKS 128
#define CHUNK (N_PTS / ACC_BLOCKS)   // 256

#define KC 32
#define XS_STRIDE 132   // 128 + 4 pad, multiple of 4 (float4-aligned rows)
#define WS_STRIDE 72    // 64 + 8 pad, multiple of 4

// ---- scratch (no allocations allowed) ----
__device__ float g_centers[NC * DIM];
__device__ float g_b2p[NC * 16];     // per-cluster ||c||^2 in 16 partials
__device__ int   g_assign[N_PTS];
__device__ float g_psum[(size_t)ACC_BLOCKS * NC * DIM];   // 16 MB partials
__device__ float g_pcnt[ACC_BLOCKS * NC];

// ============================================================================
// init: centers = data[:64], b2 partials.   grid 64, block 128
// ============================================================================
__global__ void init_kernel(const float* __restrict__ X) {
    int c = blockIdx.x;
    int t = threadIdx.x;           // 0..127, handles 4 dims via float4
    const float4* xr = (const float4*)(X + (size_t)c * DIM);
    float4 v = xr[t];
    ((float4*)(g_centers + (size_t)c * DIM))[t] = v;
    float s = v.x * v.x + v.y * v.y + v.z * v.z + v.w * v.w;
    __shared__ float red[128];
    red[t] = s;
    __syncthreads();
    for (int o = 64; o > 0; o >>= 1) {
        if (t < o) red[t] += red[t + o];
        __syncthreads();
    }
    if (t < 16) g_b2p[c * 16 + t] = (t == 0) ? red[0] : 0.0f;
}

// ============================================================================
// assign: argmin_c ( b2[c] - 2 * x . c )   (dropping constant ||x||^2)
// block tile: 128 points x 64 clusters, 256 threads, thread tile 4x8
// grid = N_PTS/128 = 256.  (proven round-15 scalar FFMA body, KC=32 static)
// ============================================================================
__global__ __launch_bounds__(256) void assign_kernel(const float* __restrict__ X) {
    __shared__ __align__(16) float Xs[KC * XS_STRIDE];
    __shared__ __align__(16) float Ws[KC * WS_STRIDE];
    __shared__ float sb2[NC];
    __shared__ float sval[128 * 8];
    __shared__ int   sidx[128 * 8];

    int tid = threadIdx.x;
    int tx = tid & 31;        // point group: points 4*tx .. 4*tx+3
    int ty = tid >> 5;        // cluster group: clusters 8*ty .. 8*ty+7
    int P0 = blockIdx.x * 128;

    if (tid < NC) {
        const float* bp = g_b2p + tid * 16;
        float s = 0.0f;
#pragma unroll
        for (int g = 0; g < 16; g++) s += bp[g];
        sb2[tid] = s;
    }

    float acc[4][8];
#pragma unroll
    for (int i = 0; i < 4; i++)
#pragma unroll
        for (int j = 0; j < 8; j++) acc[i][j] = 0.0f;

    const float4* X4 = (const float4*)X;
    const float4* W4 = (const float4*)g_centers;

    for (int kc4 = 0; kc4 < DIM / 4; kc4 += KC / 4) {
        // load 128x32 X tile, transposed into Xs[k][p]
#pragma unroll
        for (int r = 0; r < 4; r++) {
            int q = tid + r * 256;           // 0..1023
            int p = q >> 3;                  // 0..127
            int j = q & 7;                   // float4 within the 32-k chunk
            float4 v = X4[(size_t)(P0 + p) * (DIM / 4) + kc4 + j];
            int kk = j * 4;
            Xs[(kk + 0) * XS_STRIDE + p] = v.x;
            Xs[(kk + 1) * XS_STRIDE + p] = v.y;
            Xs[(kk + 2) * XS_STRIDE + p] = v.z;
            Xs[(kk + 3) * XS_STRIDE + p] = v.w;
        }
        // load 64x32 W tile, transposed into Ws[k][c]
#pragma unroll
        for (int r = 0; r < 2; r++) {
            int q = tid + r * 256;           // 0..511
            int c = q >> 3;                  // 0..63
            int j = q & 7;
            float4 v = W4[(size_t)c * (DIM / 4) + kc4 + j];
            int kk = j * 4;
            Ws[(kk + 0) * WS_STRIDE + c] = v.x;
            Ws[(kk + 1) * WS_STRIDE + c] = v.y;
            Ws[(kk + 2) * WS_STRIDE + c] = v.z;
            Ws[(kk + 3) * WS_STRIDE + c] = v.w;
        }
        __syncthreads();
#pragma unroll 8
        for (int k = 0; k < KC; k++) {
            float xr[4], wr[8];
            *(float4*)&xr[0] = *(const float4*)&Xs[k * XS_STRIDE + tx * 4];
            *(float4*)&wr[0] = *(const float4*)&Ws[k * WS_STRIDE + ty * 8];
            *(float4*)&wr[4] = *(const float4*)&Ws[k * WS_STRIDE + ty * 8 + 4];
#pragma unroll
            for (int i = 0; i < 4; i++)
#pragma unroll
                for (int j = 0; j < 8; j++)
                    acc[i][j] += xr[i] * wr[j];
        }
        __syncthreads();
    }

    // per-thread argmin over its 8 clusters (ascending index, strict <)
#pragma unroll
    for (int i = 0; i < 4; i++) {
        float mv = 3.4e38f;
        int mi = 0;
#pragma unroll
        for (int j = 0; j < 8; j++) {
            float s = sb2[ty * 8 + j] - 2.0f * acc[i][j];
            if (s < mv) { mv = s; mi = ty * 8 + j; }
        }
        int p = tx * 4 + i;
        sval[p * 8 + ty] = mv;
        sidx[p * 8 + ty] = mi;
    }
    __syncthreads();
    // reduce 8 candidates per point (ascending ty == ascending cluster ranges)
    if (tid < 128) {
        float mv = sval[tid * 8];
        int mi = sidx[tid * 8];
#pragma unroll
        for (int t = 1; t < 8; t++) {
            float v = sval[tid * 8 + t];
            if (v < mv) { mv = v; mi = sidx[tid * 8 + t]; }
        }
        g_assign[P0 + tid] = mi;
    }
}

// ============================================================================
// accumulate: per-block shared accumulator (64x512 fp32 = 128 KB), warp-private
// dim slices, 8-point batching, float4 init/writeout. grid ACC_BLOCKS, block 256.
// ============================================================================
__global__ __launch_bounds__(256) void accum_kernel(const float* __restrict__ X) {
    extern __shared__ float sm[];
    float* sacc = sm;                       // NC*DIM
    float* scnt = sm + NC * DIM;            // NC
    int*   sassign = (int*)(scnt + NC);     // CHUNK

    int tid = threadIdx.x;
    int base = blockIdx.x * CHUNK;
    for (int i = tid; i < CHUNK; i += 256) sassign[i] = g_assign[base + i];
    float4* sacc4 = (float4*)sacc;
    for (int i = tid; i < NC * DIM / 4; i += 256)
        sacc4[i] = make_float4(0.f, 0.f, 0.f, 0.f);
    for (int i = tid; i < NC; i += 256) scnt[i] = 0.0f;
    __syncthreads();

    int w = tid >> 5, lane = tid & 31;
    int doff = w * 32 + lane;               // float2 offset: warp w owns dims [64w,64w+64)
    const float2* X2 = (const float2*)X;
    float2* sacc2 = (float2*)sacc;

    for (int p = 0; p < CHUNK; p += 8) {
        float2 v[8];
        int a[8];
#pragma unroll
        for (int q = 0; q < 8; q++) {
            a[q] = sassign[p + q];
            v[q] = X2[(size_t)(base + p + q) * (DIM / 2) + doff];
        }
#pragma unroll
        for (int q = 0; q < 8; q++) {
            float2* ap = &sacc2[a[q] * (DIM / 2) + doff];
            float2 cur = *ap;
            cur.x += v[q].x; cur.y += v[q].y;
            *ap = cur;
        }
    }
    __syncthreads();
    for (int i = tid; i < CHUNK; i += 256) atomicAdd(&scnt[sassign[i]], 1.0f);
    __syncthreads();

    float4* ps4 = (float4*)(g_psum + (size_t)blockIdx.x * NC * DIM);
    for (int i = tid; i < NC * DIM / 4; i += 256) ps4[i] = sacc4[i];
    if (tid < NC) g_pcnt[blockIdx.x * NC + tid] = scnt[tid];
}

// ============================================================================
// update1: reduce partials -> new centers (keep old if empty) + b2 partials.
// grid NC*16 (cluster c = bid>>4, 32-dim group = bid&15),
// block 128 = 32 dims x 4 b-slices (32 partials each, MLP 4).
// (round-15 measured-8.8us internals + fused b2 partial; update2 deleted)
// ============================================================================
__global__ __launch_bounds__(128) void update1_kernel() {
    int c = blockIdx.x >> 4;
    int dg = blockIdx.x & 15;
    int t = threadIdx.x;
    int dl = t & 31;             // dim within the 32-dim group
    int slice = t >> 5;          // b-slice 0..3
    int d = dg * 32 + dl;
    __shared__ float red[128];
    __shared__ float part[4][32];

    // count for this cluster (redundant across dim-group blocks; L2-cheap)
    red[t] = g_pcnt[t * NC + c];             // ACC_BLOCKS == 128
    __syncthreads();
    for (int o = 64; o > 0; o >>= 1) {
        if (t < o) red[t] += red[t + o];
        __syncthreads();
    }
    float cnt = red[0];

    // partial-sum 32 of the 128 partials, MLP 4
    const float* ps = g_psum + (size_t)c * DIM + d + (size_t)(slice * 32) * (NC * DIM);
    float s0 = 0.f, s1 = 0.f, s2 = 0.f, s3 = 0.f;
#pragma unroll
    for (int b = 0; b < 32; b += 4) {
        s0 += ps[(size_t)(b + 0) * (NC * DIM)];
        s1 += ps[(size_t)(b + 1) * (NC * DIM)];
        s2 += ps[(size_t)(b + 2) * (NC * DIM)];
        s3 += ps[(size_t)(b + 3) * (NC * DIM)];
    }
    part[slice][dl] = (s0 + s1) + (s2 + s3);
    __syncthreads();

    if (slice == 0) {
        float s = (part[0][dl] + part[1][dl]) + (part[2][dl] + part[3][dl]);
        float oldc = g_centers[c * DIM + d];
        float nc = (cnt > 0.0f) ? s / cnt : oldc;
        g_centers[c * DIM + d] = nc;
        // b2 partial for this 32-dim group (threads 0..31 = one warp)
        float q = nc * nc;
#pragma unroll
        for (int o = 16; o > 0; o >>= 1) q += __shfl_down_sync(0xffffffffu, q, o);
        if (dl == 0) g_b2p[c * 16 + dg] = q;
    }
}

// ============================================================================
// final: out[p][c] = 1 / (sqrt(max(||x||^2 + ||c||^2 - 2 x.c, 0)) + 1e-8)
// same GEMM structure; ||x||^2 fused into warp ty==0 of the mainloop
// ============================================================================
__global__ __launch_bounds__(256) void final_kernel(const float* __restrict__ X,
                                                    float* __restrict__ out) {
    __shared__ __align__(16) float Xs[KC * XS_STRIDE];
    __shared__ __align__(16) float Ws[KC * WS_STRIDE];
    __shared__ float sb2[NC];
    __shared__ float sa2[128];

    int tid = threadIdx.x;
    int tx = tid & 31, ty = tid >> 5;
    int P0 = blockIdx.x * 128;

    if (tid < NC) {
        const float* bp = g_b2p + tid * 16;
        float s = 0.0f;
#pragma unroll
        for (int g = 0; g < 16; g++) s += bp[g];
        sb2[tid] = s;
    }

    float acc[4][8];
#pragma unroll
    for (int i = 0; i < 4; i++)
#pragma unroll
        for (int j = 0; j < 8; j++) acc[i][j] = 0.0f;
    float a2acc[4] = {0.f, 0.f, 0.f, 0.f};

    const float4* X4 = (const float4*)X;
    const float4* W4 = (const float4*)g_centers;

    for (int kc4 = 0; kc4 < DIM / 4; kc4 += KC / 4) {
#pragma unroll
        for (int r = 0; r < 4; r++) {
            int q = tid + r * 256;
            int p = q >> 3;
            int j = q & 7;
            float4 v = X4[(size_t)(P0 + p) * (DIM / 4) + kc4 + j];
            int kk = j * 4;
            Xs[(kk + 0) * XS_STRIDE + p] = v.x;
            Xs[(kk + 1) * XS_STRIDE + p] = v.y;
            Xs[(kk + 2) * XS_STRIDE + p] = v.z;
            Xs[(kk + 3) * XS_STRIDE + p] = v.w;
        }
#pragma unroll
        for (int r = 0; r < 2; r++) {
            int q = tid + r * 256;
            int c = q >> 3;
            int j = q & 7;
            float4 v = W4[(size_t)c * (DIM / 4) + kc4 + j];
            int kk = j * 4;
            Ws[(kk + 0) * WS_STRIDE + c] = v.x;
            Ws[(kk + 1) * WS_STRIDE + c] = v.y;
            Ws[(kk + 2) * WS_STRIDE + c] = v.z;
            Ws[(kk + 3) * WS_STRIDE + c] = v.w;
        }
        __syncthreads();
#pragma unroll 8
        for (int k = 0; k < KC; k++) {
            float xr[4], wr[8];
            *(float4*)&xr[0] = *(const float4*)&Xs[k * XS_STRIDE + tx * 4];
            *(float4*)&wr[0] = *(const float4*)&Ws[k * WS_STRIDE + ty * 8];
            *(float4*)&wr[4] = *(const float4*)&Ws[k * WS_STRIDE + ty * 8 + 4];
            if (ty == 0) {
#pragma unroll
                for (int i = 0; i < 4; i++) a2acc[i] += xr[i] * xr[i];
            }
#pragma unroll
            for (int i = 0; i < 4; i++)
#pragma unroll
                for (int j = 0; j < 8; j++)
                    acc[i][j] += xr[i] * wr[j];
        }
        __syncthreads();
    }

    if (ty == 0) {
#pragma unroll
        for (int i = 0; i < 4; i++) sa2[tx * 4 + i] = a2acc[i];
    }
    __syncthreads();

#pragma unroll
    for (int i = 0; i < 4; i++) {
        float a2 = sa2[tx * 4 + i];
        float res[8];
#pragma unroll
        for (int j = 0; j < 8; j++) {
            float d2 = a2 + sb2[ty * 8 + j] - 2.0f * acc[i][j];
            d2 = fmaxf(d2, 0.0f);
            res[j] = 1.0f / (sqrtf(d2) + 1e-8f);
        }
        float* op = out + (size_t)(P0 + tx * 4 + i) * NC + ty * 8;
        *(float4*)&op[0] = *(float4*)&res[0];
        *(float4*)&op[4] = *(float4*)&res[4];
    }
}

// ============================================================================
extern "C" void kernel_launch(void* const* d_in, const int* in_sizes, int n_in,
                              void* d_out, int out_size) {
    const float* X = (const float*)d_in[0];
    float* out = (float*)d_out;

    const int smem_acc = (NC * DIM + NC + CHUNK) * 4;   // ~132.3 KB
    cudaFuncSetAttribute(accum_kernel,
                         cudaFuncAttributeMaxDynamicSharedMemorySize, smem_acc);

    init_kernel<<<NC, 128>>>(X);
    for (int it = 0; it < KM_ITERS; it++) {
        assign_kernel<<<N_PTS / 128, 256>>>(X);
        accum_kernel<<<ACC_BLOCKS, 256, smem_acc>>>(X);
        update1_kernel<<<NC * 16, 128>>>();
    }
    final_kernel<<<N_PTS / 128, 256>>>(X, out);
}